// round 9
// baseline (speedup 1.0000x reference)
#include <cuda_runtime.h>
#include <math.h>
#include <stdint.h>

// ---------------- problem constants ----------------
#define BB 8
#define SS 384
#define IN_DIM 512
#define EE 512
#define HH 8
#define DD 64
#define BSROWS (BB*SS)        // 3072
#define ND 767                // distinct rel offsets used: j-i+383 in [0,766]
#define LDT 768               // padded leading dim for QPK/KPQ
#define REL_OFF 128           // rel_table row offset: table row = t + 128
#define SCALE_F 0.07216878364870323f   // 1/sqrt(64*3)

// ---------------- scratch (__device__ globals) ------
__device__ float g_Q[(size_t)HH*BSROWS*DD];
__device__ float g_K[(size_t)HH*BSROWS*DD];
__device__ float g_V[(size_t)HH*BSROWS*DD];
__device__ float g_PK[(size_t)HH*ND*DD];
__device__ float g_PQ[(size_t)HH*ND*DD];
__device__ float g_QPK[(size_t)HH*BSROWS*LDT];
__device__ float g_KPQ[(size_t)HH*BSROWS*LDT];
__device__ float g_vals[(size_t)BSROWS*EE];

// =================== tf32 tensor-core tile machinery =====================
// Block tile 128(M) x 128(N), K-step 32, 256 threads.
// 8 warps: wm = wid>>2 (0..1) over M 64 each, wn = wid&3 (0..3) over N 32 each.
// Warp tile 64x32 = 4 m16 atoms x 4 n8 atoms of mma.m16n8k8.tf32.
// 2-stage cp.async pipeline, dynamic smem: [A0][B0][A1][B1].
#define SM_PAD 36                       // row stride in words; conflict-free
#define TILE_WORDS (128 * SM_PAD)       // 4608
#define TC_SMEM_BYTES (4 * TILE_WORDS * 4)   // 73728

__device__ __forceinline__ uint32_t f2tf(float x) {
    uint32_t u;
    asm("cvt.rna.tf32.f32 %0, %1;" : "=r"(u) : "f"(x));
    return u;
}

__device__ __forceinline__ void mma_tf32(float* d, const uint32_t* a, const uint32_t* b) {
    asm volatile(
        "mma.sync.aligned.m16n8k8.row.col.f32.tf32.tf32.f32 "
        "{%0,%1,%2,%3}, {%4,%5,%6,%7}, {%8,%9}, {%0,%1,%2,%3};\n"
        : "+f"(d[0]), "+f"(d[1]), "+f"(d[2]), "+f"(d[3])
        : "r"(a[0]), "r"(a[1]), "r"(a[2]), "r"(a[3]),
          "r"(b[0]), "r"(b[1]));
}

__device__ __forceinline__ void cp16(uint32_t dst, const void* src, int sz) {
    asm volatile("cp.async.cg.shared.global [%0], [%1], 16, %2;\n"
                 :: "r"(dst), "l"(src), "r"(sz));
}

// Stage one 128x32 fp32 tile pair (A and B) into smem buffers via cp.async.
__device__ __forceinline__ void stage_ab(
    const float* __restrict__ A, int lda, int arows,
    const float* __restrict__ B, int ldb, int brows,
    int k0, uint32_t* sAb, uint32_t* sBb)
{
    int tid  = threadIdx.x;
    int lrow = tid & 127;
    int kb   = (tid >> 7) * 16;
    int ar = lrow < arows ? lrow : 0;
    int br = lrow < brows ? lrow : 0;
    int asz = lrow < arows ? 16 : 0;
    int bsz = lrow < brows ? 16 : 0;
    const float* ap = A + (long)ar * lda + k0 + kb;
    const float* bp = B + (long)br * ldb + k0 + kb;
    uint32_t da = (uint32_t)__cvta_generic_to_shared(&sAb[lrow * SM_PAD + kb]);
    uint32_t db = (uint32_t)__cvta_generic_to_shared(&sBb[lrow * SM_PAD + kb]);
#pragma unroll
    for (int g = 0; g < 4; g++) {
        cp16(da + g * 16, ap + g * 4, asz);
        cp16(db + g * 16, bp + g * 4, bsz);
    }
    asm volatile("cp.async.commit_group;\n");
}

// One k0=32 compute step from a resident smem tile pair (cvt at fragment load).
__device__ __forceinline__ void compute_k32(
    const uint32_t* sA, const uint32_t* sB, float acc[4][4][4],
    int wm, int wn, int lane)
{
    int rr = lane >> 2;
    int cbase = lane & 3;
#pragma unroll
    for (int k8 = 0; k8 < 4; k8++) {
        int c = k8 * 8 + cbase;
        uint32_t af[4][4], bf[4][2];
#pragma unroll
        for (int am = 0; am < 4; am++) {
            int r = wm * 64 + am * 16 + rr;
            af[am][0] = f2tf(__uint_as_float(sA[r * SM_PAD + c]));
            af[am][1] = f2tf(__uint_as_float(sA[(r + 8) * SM_PAD + c]));
            af[am][2] = f2tf(__uint_as_float(sA[r * SM_PAD + c + 4]));
            af[am][3] = f2tf(__uint_as_float(sA[(r + 8) * SM_PAD + c + 4]));
        }
#pragma unroll
        for (int an = 0; an < 4; an++) {
            int n = wn * 32 + an * 8 + rr;
            bf[an][0] = f2tf(__uint_as_float(sB[n * SM_PAD + c]));
            bf[an][1] = f2tf(__uint_as_float(sB[n * SM_PAD + c + 4]));
        }
#pragma unroll
        for (int am = 0; am < 4; am++)
#pragma unroll
            for (int an = 0; an < 4; an++)
                mma_tf32(acc[am][an], af[am], bf[an]);
    }
}

// Pipelined C_tile = A(arows x K) * B(brows x K)^T accumulation.
__device__ __forceinline__ void tc_tile(
    const float* __restrict__ A, int lda, int arows,
    const float* __restrict__ B, int ldb, int brows,
    int K, uint32_t* dyn, float acc[4][4][4])
{
    uint32_t* sAp[2] = { dyn,              dyn + 2 * TILE_WORDS };
    uint32_t* sBp[2] = { dyn + TILE_WORDS, dyn + 3 * TILE_WORDS };
    int lane = threadIdx.x & 31;
    int wid  = threadIdx.x >> 5;
    int wm = wid >> 2, wn = wid & 3;

    stage_ab(A, lda, arows, B, ldb, brows, 0, sAp[0], sBp[0]);
    int buf = 0;
    for (int k0 = 0; k0 < K; k0 += 32) {
        if (k0 + 32 < K) {
            stage_ab(A, lda, arows, B, ldb, brows, k0 + 32, sAp[buf ^ 1], sBp[buf ^ 1]);
            asm volatile("cp.async.wait_group 1;\n");
        } else {
            asm volatile("cp.async.wait_group 0;\n");
        }
        __syncthreads();
        compute_k32(sAp[buf], sBp[buf], acc, wm, wn, lane);
        __syncthreads();
        buf ^= 1;
    }
}

#define TC_PROLOG()                                                            \
    extern __shared__ uint32_t dynsm[];                                        \
    float acc[4][4][4];                                                        \
    _Pragma("unroll")                                                          \
    for (int i = 0; i < 4; i++)                                                \
        _Pragma("unroll")                                                      \
        for (int j = 0; j < 4; j++)                                            \
            _Pragma("unroll")                                                  \
            for (int r = 0; r < 4; r++) acc[i][j][r] = 0.f;                    \
    int lane = threadIdx.x & 31;                                               \
    int wid  = threadIdx.x >> 5;                                               \
    int wm = wid >> 2, wn = wid & 3;                                           \
    int rr = lane >> 2, cc2 = (lane & 3) * 2;

// ------------- merged projection kernel: Q,K,V,PK,PQ (tf32 TC) ------------
// grid.x = 336: [0,288) QKV (3 ops x 24 m x 4 n), [288,336) PK/PQ (2 x 6 x 4)
__global__ __launch_bounds__(256, 2)
void proj_all_tc(const float* __restrict__ x, const float* __restrict__ relt,
                 const float* __restrict__ Wq, const float* __restrict__ bq,
                 const float* __restrict__ Wk, const float* __restrict__ bk,
                 const float* __restrict__ Wv, const float* __restrict__ bv,
                 const float* __restrict__ Wpk, const float* __restrict__ bpk,
                 const float* __restrict__ Wpq, const float* __restrict__ bpq,
                 float* __restrict__ Qo, float* __restrict__ Ko, float* __restrict__ Vo,
                 float* __restrict__ PKo, float* __restrict__ PQo)
{
    int id = blockIdx.x;
    const float *A, *Bw, *bias; float* C;
    int M, headM, m0, n0;
    if (id < 288) {
        int op = id / 96, rem = id % 96;
        m0 = (rem >> 2) * 128; n0 = (rem & 3) * 128;
        A = x; M = BSROWS; headM = BSROWS;
        if (op == 0)      { Bw = Wq; bias = bq; C = Qo; }
        else if (op == 1) { Bw = Wk; bias = bk; C = Ko; }
        else              { Bw = Wv; bias = bv; C = Vo; }
    } else {
        int id2 = id - 288;
        int op = id2 / 24, rem = id2 % 24;
        m0 = (rem >> 2) * 128; n0 = (rem & 3) * 128;
        A = relt + (long)REL_OFF * IN_DIM; M = ND; headM = ND;
        if (op == 0) { Bw = Wpk; bias = bpk; C = PKo; }
        else         { Bw = Wpq; bias = bpq; C = PQo; }
    }

    TC_PROLOG()
    tc_tile(A + (long)m0 * IN_DIM, IN_DIM, M - m0,
            Bw + (long)n0 * IN_DIM, IN_DIM, 128,
            IN_DIM, dynsm, acc);

#pragma unroll
    for (int am = 0; am < 4; am++) {
#pragma unroll
        for (int p = 0; p < 2; p++) {
            int m = m0 + wm * 64 + am * 16 + rr + p * 8;
            if (m >= M) continue;
#pragma unroll
            for (int an = 0; an < 4; an++) {
#pragma unroll
                for (int q = 0; q < 2; q++) {
                    int n = n0 + wn * 32 + an * 8 + cc2 + q;
                    float v = acc[am][an][p * 2 + q] + bias[n];
                    C[(long)(n >> 6) * headM * 64 + (long)m * 64 + (n & 63)] = v;
                }
            }
        }
    }
}

// ------------- merged positional GEMM: QPK (z<8) / KPQ (z>=8), tf32 TC ----
// grid (6, 24, 16), band-skipped at 128x128 tile granularity.
__global__ __launch_bounds__(256, 2)
void pos_gemm_tc(const float* __restrict__ Qm, const float* __restrict__ Km,
                 const float* __restrict__ PKm, const float* __restrict__ PQm,
                 float* __restrict__ QPKo, float* __restrict__ KPQo)
{
    int n0 = blockIdx.x * 128;
    int m0 = blockIdx.y * 128;
    int z  = blockIdx.z;

    const float *A, *Bm; float* C;
    int s0 = m0 % SS;
    if (z < 8) {
        // QPK: rows i in [s0, s0+127] need t in [256-s0, 766-s0]
        if (n0 + 127 < 256 - s0 || n0 > 766 - s0) return;
        A = Qm + (long)z * BSROWS * DD; Bm = PKm + (long)z * ND * DD;
        C = QPKo + (long)z * BSROWS * LDT;
    } else {
        // KPQ: rows j in [s0, s0+127] need t in [s0, s0+510]
        if (n0 + 127 < s0 || n0 > s0 + 510) return;
        int h = z - 8;
        A = Km + (long)h * BSROWS * DD; Bm = PQm + (long)h * ND * DD;
        C = KPQo + (long)h * BSROWS * LDT;
    }

    TC_PROLOG()
    tc_tile(A + (long)m0 * DD, DD, 128,
            Bm + (long)n0 * DD, DD, ND - n0,
            DD, dynsm, acc);

#pragma unroll
    for (int am = 0; am < 4; am++) {
#pragma unroll
        for (int p = 0; p < 2; p++) {
            int m = m0 + wm * 64 + am * 16 + rr + p * 8;
#pragma unroll
            for (int an = 0; an < 4; an++) {
#pragma unroll
                for (int q = 0; q < 2; q++) {
                    int n = n0 + wn * 32 + an * 8 + cc2 + q;
                    if (n < ND)
                        C[(long)m * LDT + n] = acc[am][an][p * 2 + q];
                }
            }
        }
    }
}

// ------------- output projection: out = vals @ Wo^T + bo (tf32 TC) --------
__global__ __launch_bounds__(256, 2)
void out_gemm_tc(const float* __restrict__ A, const float* __restrict__ Bw,
                 const float* __restrict__ bias, float* __restrict__ C)
{
    int n0 = blockIdx.x * 128;
    int m0 = blockIdx.y * 128;

    TC_PROLOG()
    tc_tile(A + (long)m0 * EE, EE, 128,
            Bw + (long)n0 * EE, EE, 128,
            EE, dynsm, acc);

#pragma unroll
    for (int am = 0; am < 4; am++) {
#pragma unroll
        for (int p = 0; p < 2; p++) {
            int m = m0 + wm * 64 + am * 16 + rr + p * 8;
#pragma unroll
            for (int an = 0; an < 4; an++) {
#pragma unroll
                for (int q = 0; q < 2; q++) {
                    int n = n0 + wn * 32 + an * 8 + cc2 + q;
                    C[(long)m * IN_DIM + n] = acc[am][an][p * 2 + q] + bias[n];
                }
            }
        }
    }
}

// ---------------- fused flash attention (online softmax, fp32 SIMT) -------
#define TI 64
#define SW4(row, d4) (((row) << 4) + ((d4) ^ (((row) >> 2) & 15)))
#define ATT_SMEM_BYTES (3072 * 16 + (64 * 65 + SS) * 4)   // 67328

__global__ __launch_bounds__(256)
void attn_kernel(const float* __restrict__ Q, const float* __restrict__ K,
                 const float* __restrict__ V,
                 const float* __restrict__ QPK, const float* __restrict__ KPQ,
                 const int* __restrict__ mask, float* __restrict__ vals)
{
    extern __shared__ float4 sm4[];
    float4* sQ4 = sm4;
    float4* sK4 = sm4 + 1024;
    float4* sV4 = sm4 + 2048;
    float*  sPB = (float*)(sm4 + 3072);   // 64*65, time-shared p2c / P
    float*  sMaskF = sPB + 64 * 65;       // 384

    int i0  = blockIdx.x * TI;
    int h   = blockIdx.y;
    int b   = blockIdx.z;
    int tid = threadIdx.x;
    int tx = tid & 15, ty = tid >> 4;
    int r0 = ty * 4, c0 = tx * 4;

    long baseRow = (long)h * BSROWS + (long)b * SS;

    {
        const float4* Qg = (const float4*)(Q + (baseRow + i0) * DD);
        for (int idx = tid; idx < TI * 16; idx += 256) {
            int r = idx >> 4, d4 = idx & 15;
            sQ4[SW4(r, d4)] = Qg[idx];
        }
        for (int j = tid; j < SS; j += 256)
            sMaskF[j] = (mask[b * SS + j] == 0) ? -9.0e15f : 0.f;
    }

    float out[4][4];
    float mrun[4], runsum[4];
#pragma unroll
    for (int i = 0; i < 4; i++) {
        mrun[i] = -INFINITY; runsum[i] = 0.f;
#pragma unroll
        for (int c = 0; c < 4; c++) out[i][c] = 0.f;
    }

    for (int jt = 0; jt < SS / 64; jt++) {
        int j0 = jt * 64;
        __syncthreads();
        {
            const float4* Kg = (const float4*)(K + (baseRow + j0) * DD);
            const float4* Vg = (const float4*)(V + (baseRow + j0) * DD);
            for (int idx = tid; idx < 64 * 16; idx += 256) {
                int r = idx >> 4, d4 = idx & 15;
                sK4[SW4(r, d4)] = Kg[idx];
                sV4[SW4(r, d4)] = Vg[idx];
            }
            for (int idx = tid; idx < 64 * 64; idx += 256) {
                int jj = idx >> 6, ii = idx & 63;
                int j = j0 + jj;
                sPB[jj * 65 + ii] = KPQ[(baseRow + j) * LDT + (j - (i0 + ii) + 383)];
            }
        }
        __syncthreads();

        float l[4][4];
#pragma unroll
        for (int i = 0; i < 4; i++)
#pragma unroll
            for (int c = 0; c < 4; c++) l[i][c] = 0.f;

#pragma unroll 4
        for (int d4 = 0; d4 < 16; d4++) {
            float4 a[4], bb[4];
#pragma unroll
            for (int i = 0; i < 4; i++) a[i]  = sQ4[SW4(r0 + i, d4)];
#pragma unroll
            for (int c = 0; c < 4; c++) bb[c] = sK4[SW4(c0 + c, d4)];
#pragma unroll
            for (int i = 0; i < 4; i++)
#pragma unroll
                for (int c = 0; c < 4; c++)
                    l[i][c] += a[i].x*bb[c].x + a[i].y*bb[c].y
                             + a[i].z*bb[c].z + a[i].w*bb[c].w;
        }

#pragma unroll
        for (int i = 0; i < 4; i++) {
            int gi = i0 + r0 + i;
            const float* qpkRow = QPK + (baseRow + gi) * LDT + 383 - gi;
#pragma unroll
            for (int c = 0; c < 4; c++) {
                int j = j0 + c0 + c;
                l[i][c] = (l[i][c] + qpkRow[j] + sPB[(c0 + c) * 65 + (r0 + i)]) * SCALE_F
                          + sMaskF[j];
            }
        }
        __syncthreads();

        float tm[4];
#pragma unroll
        for (int i = 0; i < 4; i++) {
            tm[i] = fmaxf(fmaxf(l[i][0], l[i][1]), fmaxf(l[i][2], l[i][3]));
#pragma unroll
            for (int o = 1; o < 16; o <<= 1)
                tm[i] = fmaxf(tm[i], __shfl_xor_sync(0xffffffffu, tm[i], o));
        }
        float ps[4];
#pragma unroll
        for (int i = 0; i < 4; i++) {
            float newm = fmaxf(mrun[i], tm[i]);
            float f = __expf(mrun[i] - newm);
            mrun[i] = newm;
            runsum[i] *= f;
#pragma unroll
            for (int c = 0; c < 4; c++) out[i][c] *= f;
            float s = 0.f;
#pragma unroll
            for (int c = 0; c < 4; c++) {
                float p = __expf(l[i][c] - newm);
                sPB[(r0 + i) * 65 + (c0 + c)] = p;
                s += p;
            }
            ps[i] = s;
        }
#pragma unroll
        for (int i = 0; i < 4; i++) {
#pragma unroll
            for (int o = 1; o < 16; o <<= 1)
                ps[i] += __shfl_xor_sync(0xffffffffu, ps[i], o);
            runsum[i] += ps[i];
        }
        __syncthreads();

#pragma unroll 4
        for (int jj = 0; jj < 64; jj++) {
            float4 vv = sV4[SW4(jj, tx)];
            float p0 = sPB[(r0 + 0) * 65 + jj];
            float p1 = sPB[(r0 + 1) * 65 + jj];
            float p2 = sPB[(r0 + 2) * 65 + jj];
            float p3 = sPB[(r0 + 3) * 65 + jj];
            out[0][0] += p0*vv.x; out[0][1] += p0*vv.y; out[0][2] += p0*vv.z; out[0][3] += p0*vv.w;
            out[1][0] += p1*vv.x; out[1][1] += p1*vv.y; out[1][2] += p1*vv.z; out[1][3] += p1*vv.w;
            out[2][0] += p2*vv.x; out[2][1] += p2*vv.y; out[2][2] += p2*vv.z; out[2][3] += p2*vv.w;
            out[3][0] += p3*vv.x; out[3][1] += p3*vv.y; out[3][2] += p3*vv.z; out[3][3] += p3*vv.w;
        }
    }

#pragma unroll
    for (int i = 0; i < 4; i++) {
        float inv = 1.f / runsum[i];
        float4 st = make_float4(out[i][0]*inv, out[i][1]*inv, out[i][2]*inv, out[i][3]*inv);
        *(float4*)(vals + ((long)(b * SS + i0 + r0 + i)) * EE + h * DD + c0) = st;
    }
}

// ---------------- launch ----------------
extern "C" void kernel_launch(void* const* d_in, const int* in_sizes, int n_in,
                              void* d_out, int out_size)
{
    const float* x    = (const float*)d_in[0];
    const int*   mask = (const int*)  d_in[1];
    const float* Wq   = (const float*)d_in[2];
    const float* bq   = (const float*)d_in[3];
    const float* Wk   = (const float*)d_in[4];
    const float* bk   = (const float*)d_in[5];
    const float* Wv   = (const float*)d_in[6];
    const float* bv   = (const float*)d_in[7];
    const float* relt = (const float*)d_in[8];
    const float* Wpk  = (const float*)d_in[9];
    const float* bpk  = (const float*)d_in[10];
    const float* Wpq  = (const float*)d_in[11];
    const float* bpq  = (const float*)d_in[12];
    const float* Wo   = (const float*)d_in[13];
    const float* bo   = (const float*)d_in[14];
    float* out = (float*)d_out;

    float *Q, *K, *V, *PK, *PQ, *QPK, *KPQ, *VALS;
    cudaGetSymbolAddress((void**)&Q,   g_Q);
    cudaGetSymbolAddress((void**)&K,   g_K);
    cudaGetSymbolAddress((void**)&V,   g_V);
    cudaGetSymbolAddress((void**)&PK,  g_PK);
    cudaGetSymbolAddress((void**)&PQ,  g_PQ);
    cudaGetSymbolAddress((void**)&QPK, g_QPK);
    cudaGetSymbolAddress((void**)&KPQ, g_KPQ);
    cudaGetSymbolAddress((void**)&VALS, g_vals);

    cudaFuncSetAttribute(proj_all_tc, cudaFuncAttributeMaxDynamicSharedMemorySize,
                         TC_SMEM_BYTES);
    cudaFuncSetAttribute(pos_gemm_tc, cudaFuncAttributeMaxDynamicSharedMemorySize,
                         TC_SMEM_BYTES);
    cudaFuncSetAttribute(out_gemm_tc, cudaFuncAttributeMaxDynamicSharedMemorySize,
                         TC_SMEM_BYTES);
    cudaFuncSetAttribute(attn_kernel, cudaFuncAttributeMaxDynamicSharedMemorySize,
                         ATT_SMEM_BYTES);

    dim3 blk(256);

    // merged QKV + positional table projections (tf32 TC, pipelined)
    proj_all_tc<<<dim3(336), blk, TC_SMEM_BYTES>>>(x, relt, Wq, bq, Wk, bk, Wv, bv,
                                                   Wpk, bpk, Wpq, bpq, Q, K, V, PK, PQ);

    // merged per-head QPK/KPQ GEMMs (tf32 TC, band-skipped, pipelined)
    pos_gemm_tc<<<dim3(6, 24, 16), blk, TC_SMEM_BYTES>>>(Q, K, PK, PQ, QPK, KPQ);

    // fused flash attention (fp32)
    attn_kernel<<<dim3(SS / TI, HH, BB), blk, ATT_SMEM_BYTES>>>(
        Q, K, V, QPK, KPQ, mask, VALS);

    // output projection (tf32 TC, pipelined)
    out_gemm_tc<<<dim3(4, 24), blk, TC_SMEM_BYTES>>>(VALS, Wo, bo, out);
}

// round 11
// speedup vs baseline: 1.3049x; 1.3049x over previous
#include <cuda_runtime.h>
#include <math.h>
#include <stdint.h>

// ---------------- problem constants ----------------
#define BB 8
#define SS 384
#define IN_DIM 512
#define EE 512
#define HH 8
#define DD 64
#define BSROWS (BB*SS)        // 3072
#define ND 767                // distinct rel offsets used: j-i+383 in [0,766]
#define LDT 768               // padded leading dim for QPK/KPQ
#define REL_OFF 128           // rel_table row offset: table row = t + 128
#define SCALE_F 0.07216878364870323f   // 1/sqrt(64*3)

// ---------------- scratch (__device__ globals) ------
__device__ float g_Q[(size_t)HH*BSROWS*DD];
__device__ float g_K[(size_t)HH*BSROWS*DD];
__device__ float g_V[(size_t)HH*BSROWS*DD];
__device__ float g_PK[(size_t)HH*ND*DD];
__device__ float g_PQ[(size_t)HH*ND*DD];
__device__ float g_QPK[(size_t)HH*BSROWS*LDT];
__device__ float g_KPQ[(size_t)HH*BSROWS*LDT];
__device__ float g_vals[(size_t)BSROWS*EE];

// =================== tf32 tensor-core tile machinery =====================
// Block tile 128(M) x 64(N), K-step 32, 256 threads, ~3 CTAs/SM resident.
// 8 warps: wm = wid&3 over M (32 rows each), wn = wid>>2 over N (32 cols each).
// Warp tile 32x32 = 2 m16 atoms x 4 n8 atoms of mma.m16n8k8.tf32.
// cvt to tf32 happens at STAGING time (R8-proven); fragments load pre-converted.
#define SM_PAD 36   // row stride in words; 9r mod 8 cycles 16B banks -> conflict-free

__device__ __forceinline__ uint32_t f2tf(float x) {
    uint32_t u;
    asm("cvt.rna.tf32.f32 %0, %1;" : "=r"(u) : "f"(x));
    return u;
}

__device__ __forceinline__ void mma_tf32(float* d, const uint32_t* a, const uint32_t* b) {
    asm volatile(
        "mma.sync.aligned.m16n8k8.row.col.f32.tf32.tf32.f32 "
        "{%0,%1,%2,%3}, {%4,%5,%6,%7}, {%8,%9}, {%0,%1,%2,%3};\n"
        : "+f"(d[0]), "+f"(d[1]), "+f"(d[2]), "+f"(d[3])
        : "r"(a[0]), "r"(a[1]), "r"(a[2]), "r"(a[3]),
          "r"(b[0]), "r"(b[1]));
}

// C_tile = A(arows x K) * B(brows x K)^T accumulated into acc[2][4][4].
// A tile 128 x 32 staged in sA, B tile 64 x 32 staged in sB.
__device__ __forceinline__ void tc_tile(
    const float* __restrict__ A, int lda, int arows,
    const float* __restrict__ B, int ldb, int brows,
    int K, uint32_t* sA, uint32_t* sB, float acc[2][4][4])
{
    int tid  = threadIdx.x;
    int lane = tid & 31;
    int wid  = tid >> 5;
    int wm = wid & 3, wn = wid >> 2;
    int alrow = tid & 127;             // A staging row
    int akb   = (tid >> 7) * 16;       // A staging K-half
    int blrow = tid & 63;              // B staging row
    int bkb   = (tid >> 6) * 8;        // B staging K-quarter
    bool aok = alrow < arows;
    bool bok = blrow < brows;

    for (int k0 = 0; k0 < K; k0 += 32) {
#pragma unroll
        for (int g = 0; g < 4; g++) {
            float4 va = aok ? *(const float4*)(A + (long)alrow * lda + k0 + akb + g * 4)
                            : make_float4(0.f, 0.f, 0.f, 0.f);
            uint4 ua = make_uint4(f2tf(va.x), f2tf(va.y), f2tf(va.z), f2tf(va.w));
            *(uint4*)&sA[alrow * SM_PAD + akb + g * 4] = ua;
        }
#pragma unroll
        for (int g = 0; g < 2; g++) {
            float4 vb = bok ? *(const float4*)(B + (long)blrow * ldb + k0 + bkb + g * 4)
                            : make_float4(0.f, 0.f, 0.f, 0.f);
            uint4 ub = make_uint4(f2tf(vb.x), f2tf(vb.y), f2tf(vb.z), f2tf(vb.w));
            *(uint4*)&sB[blrow * SM_PAD + bkb + g * 4] = ub;
        }
        __syncthreads();

#pragma unroll
        for (int k8 = 0; k8 < 4; k8++) {
            int c  = k8 * 8 + (lane & 3);
            int rr = lane >> 2;
            uint32_t af[2][4], bf[4][2];
#pragma unroll
            for (int am = 0; am < 2; am++) {
                int r = wm * 32 + am * 16 + rr;
                af[am][0] = sA[r * SM_PAD + c];
                af[am][1] = sA[(r + 8) * SM_PAD + c];
                af[am][2] = sA[r * SM_PAD + c + 4];
                af[am][3] = sA[(r + 8) * SM_PAD + c + 4];
            }
#pragma unroll
            for (int an = 0; an < 4; an++) {
                int n = wn * 32 + an * 8 + rr;
                bf[an][0] = sB[n * SM_PAD + c];
                bf[an][1] = sB[n * SM_PAD + c + 4];
            }
#pragma unroll
            for (int am = 0; am < 2; am++)
#pragma unroll
                for (int an = 0; an < 4; an++)
                    mma_tf32(acc[am][an], af[am], bf[an]);
        }
        __syncthreads();
    }
}

#define TC_PROLOG()                                                            \
    __shared__ uint32_t sA[128 * SM_PAD];                                      \
    __shared__ uint32_t sB[64 * SM_PAD];                                       \
    float acc[2][4][4];                                                        \
    _Pragma("unroll")                                                          \
    for (int i = 0; i < 2; i++)                                                \
        _Pragma("unroll")                                                      \
        for (int j = 0; j < 4; j++)                                            \
            _Pragma("unroll")                                                  \
            for (int r = 0; r < 4; r++) acc[i][j][r] = 0.f;                    \
    int lane = threadIdx.x & 31;                                               \
    int wid  = threadIdx.x >> 5;                                               \
    int wm = wid & 3, wn = wid >> 2;                                           \
    int rr = lane >> 2, cc2 = (lane & 3) * 2;

// ------------- merged projection kernel: Q,K,V,PK,PQ (tf32 TC) ------------
// grid.x = 672: [0,576) QKV (3 ops x 24 m x 8 n), [576,672) PK/PQ (2 x 6 x 8)
__global__ __launch_bounds__(256, 2)
void proj_all_tc(const float* __restrict__ x, const float* __restrict__ relt,
                 const float* __restrict__ Wq, const float* __restrict__ bq,
                 const float* __restrict__ Wk, const float* __restrict__ bk,
                 const float* __restrict__ Wv, const float* __restrict__ bv,
                 const float* __restrict__ Wpk, const float* __restrict__ bpk,
                 const float* __restrict__ Wpq, const float* __restrict__ bpq,
                 float* __restrict__ Qo, float* __restrict__ Ko, float* __restrict__ Vo,
                 float* __restrict__ PKo, float* __restrict__ PQo)
{
    int id = blockIdx.x;
    const float *A, *Bw, *bias; float* C;
    int M, headM, m0, n0;
    if (id < 576) {
        int op = id / 192, rem = id % 192;
        m0 = (rem >> 3) * 128; n0 = (rem & 7) * 64;
        A = x; M = BSROWS; headM = BSROWS;
        if (op == 0)      { Bw = Wq; bias = bq; C = Qo; }
        else if (op == 1) { Bw = Wk; bias = bk; C = Ko; }
        else              { Bw = Wv; bias = bv; C = Vo; }
    } else {
        int id2 = id - 576;
        int op = id2 / 48, rem = id2 % 48;
        m0 = (rem >> 3) * 128; n0 = (rem & 7) * 64;
        A = relt + (long)REL_OFF * IN_DIM; M = ND; headM = ND;
        if (op == 0) { Bw = Wpk; bias = bpk; C = PKo; }
        else         { Bw = Wpq; bias = bpq; C = PQo; }
    }

    TC_PROLOG()
    tc_tile(A + (long)m0 * IN_DIM, IN_DIM, M - m0,
            Bw + (long)n0 * IN_DIM, IN_DIM, 64,
            IN_DIM, sA, sB, acc);

#pragma unroll
    for (int am = 0; am < 2; am++) {
#pragma unroll
        for (int p = 0; p < 2; p++) {
            int m = m0 + wm * 32 + am * 16 + rr + p * 8;
            if (m >= M) continue;
#pragma unroll
            for (int an = 0; an < 4; an++) {
#pragma unroll
                for (int q = 0; q < 2; q++) {
                    int n = n0 + wn * 32 + an * 8 + cc2 + q;
                    float v = acc[am][an][p * 2 + q] + bias[n];
                    C[(long)(n >> 6) * headM * 64 + (long)m * 64 + (n & 63)] = v;
                }
            }
        }
    }
}

// ------------- merged positional GEMM: QPK (z<8) / KPQ (z>=8), tf32 TC ----
// grid (12, 24, 16), band-skipped at 128(M) x 64(N) tile granularity.
__global__ __launch_bounds__(256, 2)
void pos_gemm_tc(const float* __restrict__ Qm, const float* __restrict__ Km,
                 const float* __restrict__ PKm, const float* __restrict__ PQm,
                 float* __restrict__ QPKo, float* __restrict__ KPQo)
{
    int n0 = blockIdx.x * 64;
    int m0 = blockIdx.y * 128;
    int z  = blockIdx.z;

    const float *A, *Bm; float* C;
    int s0 = m0 % SS;
    if (z < 8) {
        // QPK: rows i in [s0, s0+127] need t in [256-s0, 766-s0]
        if (n0 + 63 < 256 - s0 || n0 > 766 - s0) return;
        A = Qm + (long)z * BSROWS * DD; Bm = PKm + (long)z * ND * DD;
        C = QPKo + (long)z * BSROWS * LDT;
    } else {
        // KPQ: rows j in [s0, s0+127] need t in [s0, s0+510]
        if (n0 + 63 < s0 || n0 > s0 + 510) return;
        int h = z - 8;
        A = Km + (long)h * BSROWS * DD; Bm = PQm + (long)h * ND * DD;
        C = KPQo + (long)h * BSROWS * LDT;
    }

    TC_PROLOG()
    tc_tile(A + (long)m0 * DD, DD, 128,
            Bm + (long)n0 * DD, DD, ND - n0,
            DD, sA, sB, acc);

#pragma unroll
    for (int am = 0; am < 2; am++) {
#pragma unroll
        for (int p = 0; p < 2; p++) {
            int m = m0 + wm * 32 + am * 16 + rr + p * 8;
#pragma unroll
            for (int an = 0; an < 4; an++) {
#pragma unroll
                for (int q = 0; q < 2; q++) {
                    int n = n0 + wn * 32 + an * 8 + cc2 + q;
                    if (n < ND)
                        C[(long)m * LDT + n] = acc[am][an][p * 2 + q];
                }
            }
        }
    }
}

// ------------- output projection: out = vals @ Wo^T + bo (tf32 TC) --------
// grid (8, 24): 192 CTAs of 128x64.
__global__ __launch_bounds__(256, 2)
void out_gemm_tc(const float* __restrict__ A, const float* __restrict__ Bw,
                 const float* __restrict__ bias, float* __restrict__ C)
{
    int n0 = blockIdx.x * 64;
    int m0 = blockIdx.y * 128;

    TC_PROLOG()
    tc_tile(A + (long)m0 * EE, EE, 128,
            Bw + (long)n0 * EE, EE, 64,
            EE, sA, sB, acc);

#pragma unroll
    for (int am = 0; am < 2; am++) {
#pragma unroll
        for (int p = 0; p < 2; p++) {
            int m = m0 + wm * 32 + am * 16 + rr + p * 8;
#pragma unroll
            for (int an = 0; an < 4; an++) {
#pragma unroll
                for (int q = 0; q < 2; q++) {
                    int n = n0 + wn * 32 + an * 8 + cc2 + q;
                    C[(long)m * IN_DIM + n] = acc[am][an][p * 2 + q] + bias[n];
                }
            }
        }
    }
}

// ---------------- fused flash attention (online softmax, fp32 SIMT) -------
#define TI 64
#define SW4(row, d4) (((row) << 4) + ((d4) ^ (((row) >> 2) & 15)))
#define ATT_SMEM_BYTES (3072 * 16 + (64 * 65 + SS) * 4)   // 67328

__global__ __launch_bounds__(256)
void attn_kernel(const float* __restrict__ Q, const float* __restrict__ K,
                 const float* __restrict__ V,
                 const float* __restrict__ QPK, const float* __restrict__ KPQ,
                 const int* __restrict__ mask, float* __restrict__ vals)
{
    extern __shared__ float4 sm4[];
    float4* sQ4 = sm4;
    float4* sK4 = sm4 + 1024;
    float4* sV4 = sm4 + 2048;
    float*  sPB = (float*)(sm4 + 3072);   // 64*65, time-shared p2c / P
    float*  sMaskF = sPB + 64 * 65;       // 384

    int i0  = blockIdx.x * TI;
    int h   = blockIdx.y;
    int b   = blockIdx.z;
    int tid = threadIdx.x;
    int tx = tid & 15, ty = tid >> 4;
    int r0 = ty * 4, c0 = tx * 4;

    long baseRow = (long)h * BSROWS + (long)b * SS;

    {
        const float4* Qg = (const float4*)(Q + (baseRow + i0) * DD);
        for (int idx = tid; idx < TI * 16; idx += 256) {
            int r = idx >> 4, d4 = idx & 15;
            sQ4[SW4(r, d4)] = Qg[idx];
        }
        for (int j = tid; j < SS; j += 256)
            sMaskF[j] = (mask[b * SS + j] == 0) ? -9.0e15f : 0.f;
    }

    float out[4][4];
    float mrun[4], runsum[4];
#pragma unroll
    for (int i = 0; i < 4; i++) {
        mrun[i] = -INFINITY; runsum[i] = 0.f;
#pragma unroll
        for (int c = 0; c < 4; c++) out[i][c] = 0.f;
    }

    for (int jt = 0; jt < SS / 64; jt++) {
        int j0 = jt * 64;
        __syncthreads();
        {
            const float4* Kg = (const float4*)(K + (baseRow + j0) * DD);
            const float4* Vg = (const float4*)(V + (baseRow + j0) * DD);
            for (int idx = tid; idx < 64 * 16; idx += 256) {
                int r = idx >> 4, d4 = idx & 15;
                sK4[SW4(r, d4)] = Kg[idx];
                sV4[SW4(r, d4)] = Vg[idx];
            }
            for (int idx = tid; idx < 64 * 64; idx += 256) {
                int jj = idx >> 6, ii = idx & 63;
                int j = j0 + jj;
                sPB[jj * 65 + ii] = KPQ[(baseRow + j) * LDT + (j - (i0 + ii) + 383)];
            }
        }
        __syncthreads();

        float l[4][4];
#pragma unroll
        for (int i = 0; i < 4; i++)
#pragma unroll
            for (int c = 0; c < 4; c++) l[i][c] = 0.f;

#pragma unroll 4
        for (int d4 = 0; d4 < 16; d4++) {
            float4 a[4], bb[4];
#pragma unroll
            for (int i = 0; i < 4; i++) a[i]  = sQ4[SW4(r0 + i, d4)];
#pragma unroll
            for (int c = 0; c < 4; c++) bb[c] = sK4[SW4(c0 + c, d4)];
#pragma unroll
            for (int i = 0; i < 4; i++)
#pragma unroll
                for (int c = 0; c < 4; c++)
                    l[i][c] += a[i].x*bb[c].x + a[i].y*bb[c].y
                             + a[i].z*bb[c].z + a[i].w*bb[c].w;
        }

#pragma unroll
        for (int i = 0; i < 4; i++) {
            int gi = i0 + r0 + i;
            const float* qpkRow = QPK + (baseRow + gi) * LDT + 383 - gi;
#pragma unroll
            for (int c = 0; c < 4; c++) {
                int j = j0 + c0 + c;
                l[i][c] = (l[i][c] + qpkRow[j] + sPB[(c0 + c) * 65 + (r0 + i)]) * SCALE_F
                          + sMaskF[j];
            }
        }
        __syncthreads();

        float tm[4];
#pragma unroll
        for (int i = 0; i < 4; i++) {
            tm[i] = fmaxf(fmaxf(l[i][0], l[i][1]), fmaxf(l[i][2], l[i][3]));
#pragma unroll
            for (int o = 1; o < 16; o <<= 1)
                tm[i] = fmaxf(tm[i], __shfl_xor_sync(0xffffffffu, tm[i], o));
        }
        float ps[4];
#pragma unroll
        for (int i = 0; i < 4; i++) {
            float newm = fmaxf(mrun[i], tm[i]);
            float f = __expf(mrun[i] - newm);
            mrun[i] = newm;
            runsum[i] *= f;
#pragma unroll
            for (int c = 0; c < 4; c++) out[i][c] *= f;
            float s = 0.f;
#pragma unroll
            for (int c = 0; c < 4; c++) {
                float p = __expf(l[i][c] - newm);
                sPB[(r0 + i) * 65 + (c0 + c)] = p;
                s += p;
            }
            ps[i] = s;
        }
#pragma unroll
        for (int i = 0; i < 4; i++) {
#pragma unroll
            for (int o = 1; o < 16; o <<= 1)
                ps[i] += __shfl_xor_sync(0xffffffffu, ps[i], o);
            runsum[i] += ps[i];
        }
        __syncthreads();

#pragma unroll 4
        for (int jj = 0; jj < 64; jj++) {
            float4 vv = sV4[SW4(jj, tx)];
            float p0 = sPB[(r0 + 0) * 65 + jj];
            float p1 = sPB[(r0 + 1) * 65 + jj];
            float p2 = sPB[(r0 + 2) * 65 + jj];
            float p3 = sPB[(r0 + 3) * 65 + jj];
            out[0][0] += p0*vv.x; out[0][1] += p0*vv.y; out[0][2] += p0*vv.z; out[0][3] += p0*vv.w;
            out[1][0] += p1*vv.x; out[1][1] += p1*vv.y; out[1][2] += p1*vv.z; out[1][3] += p1*vv.w;
            out[2][0] += p2*vv.x; out[2][1] += p2*vv.y; out[2][2] += p2*vv.z; out[2][3] += p2*vv.w;
            out[3][0] += p3*vv.x; out[3][1] += p3*vv.y; out[3][2] += p3*vv.z; out[3][3] += p3*vv.w;
        }
    }

#pragma unroll
    for (int i = 0; i < 4; i++) {
        float inv = 1.f / runsum[i];
        float4 st = make_float4(out[i][0]*inv, out[i][1]*inv, out[i][2]*inv, out[i][3]*inv);
        *(float4*)(vals + ((long)(b * SS + i0 + r0 + i)) * EE + h * DD + c0) = st;
    }
}

// ---------------- launch ----------------
extern "C" void kernel_launch(void* const* d_in, const int* in_sizes, int n_in,
                              void* d_out, int out_size)
{
    const float* x    = (const float*)d_in[0];
    const int*   mask = (const int*)  d_in[1];
    const float* Wq   = (const float*)d_in[2];
    const float* bq   = (const float*)d_in[3];
    const float* Wk   = (const float*)d_in[4];
    const float* bk   = (const float*)d_in[5];
    const float* Wv   = (const float*)d_in[6];
    const float* bv   = (const float*)d_in[7];
    const float* relt = (const float*)d_in[8];
    const float* Wpk  = (const float*)d_in[9];
    const float* bpk  = (const float*)d_in[10];
    const float* Wpq  = (const float*)d_in[11];
    const float* bpq  = (const float*)d_in[12];
    const float* Wo   = (const float*)d_in[13];
    const float* bo   = (const float*)d_in[14];
    float* out = (float*)d_out;

    float *Q, *K, *V, *PK, *PQ, *QPK, *KPQ, *VALS;
    cudaGetSymbolAddress((void**)&Q,   g_Q);
    cudaGetSymbolAddress((void**)&K,   g_K);
    cudaGetSymbolAddress((void**)&V,   g_V);
    cudaGetSymbolAddress((void**)&PK,  g_PK);
    cudaGetSymbolAddress((void**)&PQ,  g_PQ);
    cudaGetSymbolAddress((void**)&QPK, g_QPK);
    cudaGetSymbolAddress((void**)&KPQ, g_KPQ);
    cudaGetSymbolAddress((void**)&VALS, g_vals);

    cudaFuncSetAttribute(attn_kernel, cudaFuncAttributeMaxDynamicSharedMemorySize,
                         ATT_SMEM_BYTES);

    dim3 blk(256);

    // merged QKV + positional table projections (tf32 TC)
    proj_all_tc<<<dim3(672), blk>>>(x, relt, Wq, bq, Wk, bk, Wv, bv,
                                    Wpk, bpk, Wpq, bpq, Q, K, V, PK, PQ);

    // merged per-head QPK/KPQ GEMMs (tf32 TC, band-skipped)
    pos_gemm_tc<<<dim3(12, 24, 16), blk>>>(Q, K, PK, PQ, QPK, KPQ);

    // fused flash attention (fp32)
    attn_kernel<<<dim3(SS / TI, HH, BB), blk, ATT_SMEM_BYTES>>>(
        Q, K, V, QPK, KPQ, mask, VALS);

    // output projection (tf32 TC)
    out_gemm_tc<<<dim3(8, 24), blk>>>(VALS, Wo, bo, out);
}

// round 15
// speedup vs baseline: 1.6216x; 1.2426x over previous
#include <cuda_runtime.h>
#include <math.h>
#include <stdint.h>

// ---------------- problem constants ----------------
#define BB 8
#define SS 384
#define IN_DIM 512
#define EE 512
#define HH 8
#define DD 64
#define BSROWS (BB*SS)        // 3072
#define ND 767                // distinct rel offsets used: j-i+383 in [0,766]
#define LDT 768               // padded leading dim for QPK/KPQ
#define REL_OFF 128           // rel_table row offset: table row = t + 128
#define SCALE_F 0.07216878364870323f   // 1/sqrt(64*3)

// ---------------- scratch (__device__ globals) ------
__device__ float g_Q[(size_t)HH*BSROWS*DD];
__device__ float g_K[(size_t)HH*BSROWS*DD];
__device__ float g_V[(size_t)HH*BSROWS*DD];
__device__ float g_PK[(size_t)HH*ND*DD];
__device__ float g_PQ[(size_t)HH*ND*DD];
__device__ float g_QPK[(size_t)HH*BSROWS*LDT];
__device__ float g_KPQ[(size_t)HH*BSROWS*LDT];
__device__ float g_vals[(size_t)BSROWS*EE];

// =================== tf32 tensor-core tile machinery =====================
// Block tile 64(M) x 64(N), K-step 32, 256 threads, ~3 CTAs/SM resident.
// 8 warps: wm = wid&3 over M (16 rows each), wn = wid>>2 over N (32 cols each).
// Warp tile 16x32 = 1 m16 atom x 4 n8 atoms of mma.m16n8k8.tf32.
// Register-prefetch double buffering: LDG for k0+32 issued before compute(k0).
// cvt to tf32 at staging time (R8-proven numerics).
#define SM_PAD 36   // row stride in words

__device__ __forceinline__ uint32_t f2tf(float x) {
    uint32_t u;
    asm("cvt.rna.tf32.f32 %0, %1;" : "=r"(u) : "f"(x));
    return u;
}

__device__ __forceinline__ void mma_tf32(float* d, const uint32_t* a, const uint32_t* b) {
    asm volatile(
        "mma.sync.aligned.m16n8k8.row.col.f32.tf32.tf32.f32 "
        "{%0,%1,%2,%3}, {%4,%5,%6,%7}, {%8,%9}, {%0,%1,%2,%3};\n"
        : "+f"(d[0]), "+f"(d[1]), "+f"(d[2]), "+f"(d[3])
        : "r"(a[0]), "r"(a[1]), "r"(a[2]), "r"(a[3]),
          "r"(b[0]), "r"(b[1]));
}

// C_tile(64x64) = A(arows x K) * B(brows x K)^T accumulated into acc[4][4].
__device__ __forceinline__ void tc_tile64(
    const float* __restrict__ A, int lda, int arows,
    const float* __restrict__ B, int ldb, int brows,
    int K, uint32_t* sA, uint32_t* sB, float acc[4][4])
{
    int tid  = threadIdx.x;
    int lane = tid & 31;
    int wid  = tid >> 5;
    int wm = wid & 3, wn = wid >> 2;
    int srow = tid >> 2;           // 0..63 staging row
    int sc   = (tid & 3) * 4;      // staging col quad: 0,4,8,12 (+16 for 2nd)
    bool aok = srow < arows;
    bool bok = srow < brows;
    const float4 z4 = make_float4(0.f, 0.f, 0.f, 0.f);

    const float* Ar = A + (long)srow * lda + sc;
    const float* Br = B + (long)srow * ldb + sc;

    // initial prefetch (k0 = 0)
    float4 pa0 = aok ? *(const float4*)(Ar)      : z4;
    float4 pa1 = aok ? *(const float4*)(Ar + 16) : z4;
    float4 pb0 = bok ? *(const float4*)(Br)      : z4;
    float4 pb1 = bok ? *(const float4*)(Br + 16) : z4;

    for (int k0 = 0; k0 < K; k0 += 32) {
        // stage prefetched regs into smem (cvt to tf32 here)
        *(uint4*)&sA[srow * SM_PAD + sc]      =
            make_uint4(f2tf(pa0.x), f2tf(pa0.y), f2tf(pa0.z), f2tf(pa0.w));
        *(uint4*)&sA[srow * SM_PAD + sc + 16] =
            make_uint4(f2tf(pa1.x), f2tf(pa1.y), f2tf(pa1.z), f2tf(pa1.w));
        *(uint4*)&sB[srow * SM_PAD + sc]      =
            make_uint4(f2tf(pb0.x), f2tf(pb0.y), f2tf(pb0.z), f2tf(pb0.w));
        *(uint4*)&sB[srow * SM_PAD + sc + 16] =
            make_uint4(f2tf(pb1.x), f2tf(pb1.y), f2tf(pb1.z), f2tf(pb1.w));
        __syncthreads();

        // issue next tile's LDG now — latency overlaps compute below
        if (k0 + 32 < K) {
            const float* An = Ar + k0 + 32;
            const float* Bn = Br + k0 + 32;
            pa0 = aok ? *(const float4*)(An)      : z4;
            pa1 = aok ? *(const float4*)(An + 16) : z4;
            pb0 = bok ? *(const float4*)(Bn)      : z4;
            pb1 = bok ? *(const float4*)(Bn + 16) : z4;
        }

        // compute from resident smem tile
#pragma unroll
        for (int k8 = 0; k8 < 4; k8++) {
            int c  = k8 * 8 + (lane & 3);
            int rr = lane >> 2;
            uint32_t af[4], bf[4][2];
            int r = wm * 16 + rr;
            af[0] = sA[r * SM_PAD + c];
            af[1] = sA[(r + 8) * SM_PAD + c];
            af[2] = sA[r * SM_PAD + c + 4];
            af[3] = sA[(r + 8) * SM_PAD + c + 4];
#pragma unroll
            for (int an = 0; an < 4; an++) {
                int n = wn * 32 + an * 8 + rr;
                bf[an][0] = sB[n * SM_PAD + c];
                bf[an][1] = sB[n * SM_PAD + c + 4];
            }
#pragma unroll
            for (int an = 0; an < 4; an++)
                mma_tf32(acc[an], af, bf[an]);
        }
        __syncthreads();
    }
}

#define TC_PROLOG()                                                            \
    __shared__ uint32_t sA[64 * SM_PAD];                                       \
    __shared__ uint32_t sB[64 * SM_PAD];                                       \
    float acc[4][4];                                                           \
    _Pragma("unroll")                                                          \
    for (int j = 0; j < 4; j++)                                                \
        _Pragma("unroll")                                                      \
        for (int r = 0; r < 4; r++) acc[j][r] = 0.f;                           \
    int lane = threadIdx.x & 31;                                               \
    int wid  = threadIdx.x >> 5;                                               \
    int wm = wid & 3, wn = wid >> 2;                                           \
    int rr = lane >> 2, cc2 = (lane & 3) * 2;

// ------------- merged projection kernel: Q,K,V,PK,PQ (tf32 TC) ------------
// grid.x = 1344: [0,1152) QKV (3 ops x 48 m x 8 n), [1152,1344) PK/PQ (2x12x8)
__global__ __launch_bounds__(256, 3)
void proj_all_tc(const float* __restrict__ x, const float* __restrict__ relt,
                 const float* __restrict__ Wq, const float* __restrict__ bq,
                 const float* __restrict__ Wk, const float* __restrict__ bk,
                 const float* __restrict__ Wv, const float* __restrict__ bv,
                 const float* __restrict__ Wpk, const float* __restrict__ bpk,
                 const float* __restrict__ Wpq, const float* __restrict__ bpq,
                 float* __restrict__ Qo, float* __restrict__ Ko, float* __restrict__ Vo,
                 float* __restrict__ PKo, float* __restrict__ PQo)
{
    int id = blockIdx.x;
    const float *A, *Bw, *bias; float* C;
    int M, headM, m0, n0;
    if (id < 1152) {
        int op = id / 384, rem = id % 384;
        m0 = (rem >> 3) * 64; n0 = (rem & 7) * 64;
        A = x; M = BSROWS; headM = BSROWS;
        if (op == 0)      { Bw = Wq; bias = bq; C = Qo; }
        else if (op == 1) { Bw = Wk; bias = bk; C = Ko; }
        else              { Bw = Wv; bias = bv; C = Vo; }
    } else {
        int id2 = id - 1152;
        int op = id2 / 96, rem = id2 % 96;
        m0 = (rem >> 3) * 64; n0 = (rem & 7) * 64;
        A = relt + (long)REL_OFF * IN_DIM; M = ND; headM = ND;
        if (op == 0) { Bw = Wpk; bias = bpk; C = PKo; }
        else         { Bw = Wpq; bias = bpq; C = PQo; }
    }

    TC_PROLOG()
    tc_tile64(A + (long)m0 * IN_DIM, IN_DIM, M - m0,
              Bw + (long)n0 * IN_DIM, IN_DIM, 64,
              IN_DIM, sA, sB, acc);

#pragma unroll
    for (int p = 0; p < 2; p++) {
        int m = m0 + wm * 16 + rr + p * 8;
        if (m >= M) continue;
#pragma unroll
        for (int an = 0; an < 4; an++) {
#pragma unroll
            for (int q = 0; q < 2; q++) {
                int n = n0 + wn * 32 + an * 8 + cc2 + q;
                float v = acc[an][p * 2 + q] + bias[n];
                C[(long)(n >> 6) * headM * 64 + (long)m * 64 + (n & 63)] = v;
            }
        }
    }
}

// ------------- merged positional GEMM: QPK (z<8) / KPQ (z>=8), tf32 TC ----
// grid (12, 48, 16), band-skipped at 64x64 tile granularity.
__global__ __launch_bounds__(256, 3)
void pos_gemm_tc(const float* __restrict__ Qm, const float* __restrict__ Km,
                 const float* __restrict__ PKm, const float* __restrict__ PQm,
                 float* __restrict__ QPKo, float* __restrict__ KPQo)
{
    int n0 = blockIdx.x * 64;
    int m0 = blockIdx.y * 64;
    int z  = blockIdx.z;

    const float *A, *Bm; float* C;
    int s0 = m0 % SS;
    if (z < 8) {
        // QPK: rows i in [s0, s0+63] need t in [320-s0, 766-s0]
        if (n0 + 63 < 320 - s0 || n0 > 766 - s0) return;
        A = Qm + (long)z * BSROWS * DD; Bm = PKm + (long)z * ND * DD;
        C = QPKo + (long)z * BSROWS * LDT;
    } else {
        // KPQ: rows j in [s0, s0+63] need t in [s0, s0+446]
        if (n0 + 63 < s0 || n0 > s0 + 446) return;
        int h = z - 8;
        A = Km + (long)h * BSROWS * DD; Bm = PQm + (long)h * ND * DD;
        C = KPQo + (long)h * BSROWS * LDT;
    }

    TC_PROLOG()
    tc_tile64(A + (long)m0 * DD, DD, 64,
              Bm + (long)n0 * DD, DD, ND - n0,
              DD, sA, sB, acc);

#pragma unroll
    for (int p = 0; p < 2; p++) {
        int m = m0 + wm * 16 + rr + p * 8;
#pragma unroll
        for (int an = 0; an < 4; an++) {
#pragma unroll
            for (int q = 0; q < 2; q++) {
                int n = n0 + wn * 32 + an * 8 + cc2 + q;
                if (n < ND)
                    C[(long)m * LDT + n] = acc[an][p * 2 + q];
            }
        }
    }
}

// ------------- output projection: out = vals @ Wo^T + bo (tf32 TC) --------
// grid (8, 48): 384 CTAs of 64x64.
__global__ __launch_bounds__(256, 3)
void out_gemm_tc(const float* __restrict__ A, const float* __restrict__ Bw,
                 const float* __restrict__ bias, float* __restrict__ C)
{
    int n0 = blockIdx.x * 64;
    int m0 = blockIdx.y * 64;

    TC_PROLOG()
    tc_tile64(A + (long)m0 * EE, EE, 64,
              Bw + (long)n0 * EE, EE, 64,
              EE, sA, sB, acc);

#pragma unroll
    for (int p = 0; p < 2; p++) {
        int m = m0 + wm * 16 + rr + p * 8;
#pragma unroll
        for (int an = 0; an < 4; an++) {
#pragma unroll
            for (int q = 0; q < 2; q++) {
                int n = n0 + wn * 32 + an * 8 + cc2 + q;
                C[(long)m * IN_DIM + n] = acc[an][p * 2 + q] + bias[n];
            }
        }
    }
}

// ---------------- fused flash attention (online softmax, fp32 SIMT) -------
#define TI 64
#define SW4(row, d4) (((row) << 4) + ((d4) ^ (((row) >> 2) & 15)))
#define ATT_SMEM_BYTES (3072 * 16 + (64 * 65 + SS) * 4)   // 67328

__global__ __launch_bounds__(256)
void attn_kernel(const float* __restrict__ Q, const float* __restrict__ K,
                 const float* __restrict__ V,
                 const float* __restrict__ QPK, const float* __restrict__ KPQ,
                 const int* __restrict__ mask, float* __restrict__ vals)
{
    extern __shared__ float4 sm4[];
    float4* sQ4 = sm4;
    float4* sK4 = sm4 + 1024;
    float4* sV4 = sm4 + 2048;
    float*  sPB = (float*)(sm4 + 3072);   // 64*65, time-shared p2c / P
    float*  sMaskF = sPB + 64 * 65;       // 384

    int i0  = blockIdx.x * TI;
    int h   = blockIdx.y;
    int b   = blockIdx.z;
    int tid = threadIdx.x;
    int tx = tid & 15, ty = tid >> 4;
    int r0 = ty * 4, c0 = tx * 4;

    long baseRow = (long)h * BSROWS + (long)b * SS;

    {
        const float4* Qg = (const float4*)(Q + (baseRow + i0) * DD);
        for (int idx = tid; idx < TI * 16; idx += 256) {
            int r = idx >> 4, d4 = idx & 15;
            sQ4[SW4(r, d4)] = Qg[idx];
        }
        for (int j = tid; j < SS; j += 256)
            sMaskF[j] = (mask[b * SS + j] == 0) ? -9.0e15f : 0.f;
    }

    float out[4][4];
    float mrun[4], runsum[4];
#pragma unroll
    for (int i = 0; i < 4; i++) {
        mrun[i] = -INFINITY; runsum[i] = 0.f;
#pragma unroll
        for (int c = 0; c < 4; c++) out[i][c] = 0.f;
    }

    for (int jt = 0; jt < SS / 64; jt++) {
        int j0 = jt * 64;
        __syncthreads();
        {
            const float4* Kg = (const float4*)(K + (baseRow + j0) * DD);
            const float4* Vg = (const float4*)(V + (baseRow + j0) * DD);
            for (int idx = tid; idx < 64 * 16; idx += 256) {
                int r = idx >> 4, d4 = idx & 15;
                sK4[SW4(r, d4)] = Kg[idx];
                sV4[SW4(r, d4)] = Vg[idx];
            }
            for (int idx = tid; idx < 64 * 64; idx += 256) {
                int jj = idx >> 6, ii = idx & 63;
                int j = j0 + jj;
                sPB[jj * 65 + ii] = KPQ[(baseRow + j) * LDT + (j - (i0 + ii) + 383)];
            }
        }
        __syncthreads();

        float l[4][4];
#pragma unroll
        for (int i = 0; i < 4; i++)
#pragma unroll
            for (int c = 0; c < 4; c++) l[i][c] = 0.f;

#pragma unroll 4
        for (int d4 = 0; d4 < 16; d4++) {
            float4 a[4], bb[4];
#pragma unroll
            for (int i = 0; i < 4; i++) a[i]  = sQ4[SW4(r0 + i, d4)];
#pragma unroll
            for (int c = 0; c < 4; c++) bb[c] = sK4[SW4(c0 + c, d4)];
#pragma unroll
            for (int i = 0; i < 4; i++)
#pragma unroll
                for (int c = 0; c < 4; c++)
                    l[i][c] += a[i].x*bb[c].x + a[i].y*bb[c].y
                             + a[i].z*bb[c].z + a[i].w*bb[c].w;
        }

#pragma unroll
        for (int i = 0; i < 4; i++) {
            int gi = i0 + r0 + i;
            const float* qpkRow = QPK + (baseRow + gi) * LDT + 383 - gi;
#pragma unroll
            for (int c = 0; c < 4; c++) {
                int j = j0 + c0 + c;
                l[i][c] = (l[i][c] + qpkRow[j] + sPB[(c0 + c) * 65 + (r0 + i)]) * SCALE_F
                          + sMaskF[j];
            }
        }
        __syncthreads();

        float tm[4];
#pragma unroll
        for (int i = 0; i < 4; i++) {
            tm[i] = fmaxf(fmaxf(l[i][0], l[i][1]), fmaxf(l[i][2], l[i][3]));
#pragma unroll
            for (int o = 1; o < 16; o <<= 1)
                tm[i] = fmaxf(tm[i], __shfl_xor_sync(0xffffffffu, tm[i], o));
        }
        float ps[4];
#pragma unroll
        for (int i = 0; i < 4; i++) {
            float newm = fmaxf(mrun[i], tm[i]);
            float f = __expf(mrun[i] - newm);
            mrun[i] = newm;
            runsum[i] *= f;
#pragma unroll
            for (int c = 0; c < 4; c++) out[i][c] *= f;
            float s = 0.f;
#pragma unroll
            for (int c = 0; c < 4; c++) {
                float p = __expf(l[i][c] - newm);
                sPB[(r0 + i) * 65 + (c0 + c)] = p;
                s += p;
            }
            ps[i] = s;
        }
#pragma unroll
        for (int i = 0; i < 4; i++) {
#pragma unroll
            for (int o = 1; o < 16; o <<= 1)
                ps[i] += __shfl_xor_sync(0xffffffffu, ps[i], o);
            runsum[i] += ps[i];
        }
        __syncthreads();

#pragma unroll 4
        for (int jj = 0; jj < 64; jj++) {
            float4 vv = sV4[SW4(jj, tx)];
            float p0 = sPB[(r0 + 0) * 65 + jj];
            float p1 = sPB[(r0 + 1) * 65 + jj];
            float p2 = sPB[(r0 + 2) * 65 + jj];
            float p3 = sPB[(r0 + 3) * 65 + jj];
            out[0][0] += p0*vv.x; out[0][1] += p0*vv.y; out[0][2] += p0*vv.z; out[0][3] += p0*vv.w;
            out[1][0] += p1*vv.x; out[1][1] += p1*vv.y; out[1][2] += p1*vv.z; out[1][3] += p1*vv.w;
            out[2][0] += p2*vv.x; out[2][1] += p2*vv.y; out[2][2] += p2*vv.z; out[2][3] += p2*vv.w;
            out[3][0] += p3*vv.x; out[3][1] += p3*vv.y; out[3][2] += p3*vv.z; out[3][3] += p3*vv.w;
        }
    }

#pragma unroll
    for (int i = 0; i < 4; i++) {
        float inv = 1.f / runsum[i];
        float4 st = make_float4(out[i][0]*inv, out[i][1]*inv, out[i][2]*inv, out[i][3]*inv);
        *(float4*)(vals + ((long)(b * SS + i0 + r0 + i)) * EE + h * DD + c0) = st;
    }
}

// ---------------- launch ----------------
extern "C" void kernel_launch(void* const* d_in, const int* in_sizes, int n_in,
                              void* d_out, int out_size)
{
    const float* x    = (const float*)d_in[0];
    const int*   mask = (const int*)  d_in[1];
    const float* Wq   = (const float*)d_in[2];
    const float* bq   = (const float*)d_in[3];
    const float* Wk   = (const float*)d_in[4];
    const float* bk   = (const float*)d_in[5];
    const float* Wv   = (const float*)d_in[6];
    const float* bv   = (const float*)d_in[7];
    const float* relt = (const float*)d_in[8];
    const float* Wpk  = (const float*)d_in[9];
    const float* bpk  = (const float*)d_in[10];
    const float* Wpq  = (const float*)d_in[11];
    const float* bpq  = (const float*)d_in[12];
    const float* Wo   = (const float*)d_in[13];
    const float* bo   = (const float*)d_in[14];
    float* out = (float*)d_out;

    float *Q, *K, *V, *PK, *PQ, *QPK, *KPQ, *VALS;
    cudaGetSymbolAddress((void**)&Q,   g_Q);
    cudaGetSymbolAddress((void**)&K,   g_K);
    cudaGetSymbolAddress((void**)&V,   g_V);
    cudaGetSymbolAddress((void**)&PK,  g_PK);
    cudaGetSymbolAddress((void**)&PQ,  g_PQ);
    cudaGetSymbolAddress((void**)&QPK, g_QPK);
    cudaGetSymbolAddress((void**)&KPQ, g_KPQ);
    cudaGetSymbolAddress((void**)&VALS, g_vals);

    cudaFuncSetAttribute(attn_kernel, cudaFuncAttributeMaxDynamicSharedMemorySize,
                         ATT_SMEM_BYTES);

    dim3 blk(256);

    // merged QKV + positional table projections (tf32 TC, reg-prefetch)
    proj_all_tc<<<dim3(1344), blk>>>(x, relt, Wq, bq, Wk, bk, Wv, bv,
                                     Wpk, bpk, Wpq, bpq, Q, K, V, PK, PQ);

    // merged per-head QPK/KPQ GEMMs (tf32 TC, band-skipped, reg-prefetch)
    pos_gemm_tc<<<dim3(12, 48, 16), blk>>>(Q, K, PK, PQ, QPK, KPQ);

    // fused flash attention (fp32)
    attn_kernel<<<dim3(SS / TI, HH, BB), blk, ATT_SMEM_BYTES>>>(
        Q, K, V, QPK, KPQ, mask, VALS);

    // output projection (tf32 TC, reg-prefetch)
    out_gemm_tc<<<dim3(8, 48), blk>>>(VALS, Wo, bo, out);
}